// round 7
// baseline (speedup 1.0000x reference)
#include <cuda_runtime.h>
#include <cstdint>
#include <cstddef>

// Problem constants
#define BT      65536          // B*T rows
#define DDIM    64
#define KCODES  1024
#define BM      64             // rows per block
#define BN      128            // codes per chunk
#define NCH     (KCODES / BN)  // 8 chunks

// Dynamic smem layout (bytes):
//   zDup  : [64 k][64 row] float2 (duplicated)   = 32768
//   eBuf  : 2 x [64 k][2 region][16 tx][4] float = 65536
//   zn    : 64 float                             =   256
//   idx_s : 64 int                               =   256
//   red   : 256 float                            =  1024
#define SM_ZDUP   0
#define SM_EBUF   32768
#define SM_ZN     (32768 + 65536)
#define SM_IDX    (SM_ZN + 256)
#define SM_RED    (SM_IDX + 256)
#define SMEM_TOTAL (SM_RED + 1024)   // 99840 bytes

__device__ float g_enorm[KCODES];
__device__ float g_embT[KCODES * DDIM];   // transposed/region-split emb
__device__ float g_partial[BT / BM];      // 1024 per-block loss partials

// packed fp32x2 FMA: lanes are IEEE fp32 fma.rn — identical to two __fmaf_rn
#define FMA2(acc, a, b) \
    asm("fma.rn.f32x2 %0, %1, %2, %0;" : "+l"(acc) : "l"(a), "l"(b))

#define CP_ASYNC16(dst_u32, src_ptr) \
    asm volatile("cp.async.ca.shared.global [%0], [%1], 16;" :: "r"(dst_u32), "l"(src_ptr))
#define CP_COMMIT()  asm volatile("cp.async.commit_group;")
#define CP_WAIT0()   asm volatile("cp.async.wait_group 0;" ::: "memory")

// ---------------------------------------------------------------------------
// Prep: per-code squared norms (sequential fp32, reference order) + transpose
// emb into the region-split [chunk][k][region][tx][4] layout for packed LDS.
// ---------------------------------------------------------------------------
__global__ __launch_bounds__(128) void prep_kernel(const float* __restrict__ emb) {
    int c = blockIdx.x * 128 + threadIdx.x;     // grid = 8 -> c in [0,1024)
    const float* e = emb + (size_t)c * DDIM;
    float v[DDIM];
    float s = 0.0f;
    #pragma unroll
    for (int q = 0; q < 16; ++q) {
        float4 t = *(const float4*)(e + q * 4);
        v[q*4+0] = t.x; v[q*4+1] = t.y; v[q*4+2] = t.z; v[q*4+3] = t.w;
        s = __fadd_rn(s, __fmul_rn(t.x, t.x));
        s = __fadd_rn(s, __fmul_rn(t.y, t.y));
        s = __fadd_rn(s, __fmul_rn(t.z, t.z));
        s = __fadd_rn(s, __fmul_rn(t.w, t.w));
    }
    g_enorm[c] = s;

    int ch     = c >> 7;        // chunk of 128 codes
    int within = c & 127;
    int txg    = within >> 3;   // 0..15
    int j      = within & 7;    // 0..7
    int base   = ch * (DDIM * BN) + (j >> 2) * 64 + txg * 4 + (j & 3);
    #pragma unroll
    for (int k = 0; k < DDIM; ++k)
        g_embT[base + k * BN] = v[k];
}

// ---------------------------------------------------------------------------
// Main VQ kernel: packed-f32x2 distance GEMM + argmin + gather + loss partial
// ---------------------------------------------------------------------------
__global__ __launch_bounds__(256, 2) void vq_main(const float* __restrict__ z,
                                                  const float* __restrict__ emb,
                                                  float* __restrict__ out_zq,
                                                  float* __restrict__ out_idx) {
    extern __shared__ char smem_raw[];
    float2* zDup  = (float2*)(smem_raw + SM_ZDUP);   // [k][row], duplicated
    float*  eBuf  = (float*) (smem_raw + SM_EBUF);   // 2 x 8192 floats
    float*  zn    = (float*) (smem_raw + SM_ZN);
    int*    idx_s = (int*)   (smem_raw + SM_IDX);
    float*  red   = (float*) (smem_raw + SM_RED);

    const int tid  = threadIdx.x;
    const int tx   = tid & 15;     // code group (8 codes each)
    const int ty   = tid >> 4;     // row group  (4 rows each)
    const int row0 = blockIdx.x * BM;

    // ---- issue cp.async for chunk 0 (32KB, linear copy) ----
    {
        float* dstf = eBuf;
        #pragma unroll
        for (int i = 0; i < 8; ++i) {
            int u = tid + i * 256;
            unsigned d = (unsigned)__cvta_generic_to_shared(dstf + u * 4);
            CP_ASYNC16(d, g_embT + u * 4);
        }
        CP_COMMIT();
    }

    // ---- load z tile (64x64), store duplicated-transposed ----
    #pragma unroll
    for (int i = 0; i < 4; ++i) {
        int f  = tid + i * 256;         // float4 index 0..1023
        int r  = f >> 4;                // row 0..63
        int d0 = (f & 15) << 2;         // d 0..60
        float4 v = *(const float4*)(z + (size_t)(row0 + r) * DDIM + d0);
        zDup[(d0 + 0) * BM + r] = make_float2(v.x, v.x);
        zDup[(d0 + 1) * BM + r] = make_float2(v.y, v.y);
        zDup[(d0 + 2) * BM + r] = make_float2(v.z, v.z);
        zDup[(d0 + 3) * BM + r] = make_float2(v.w, v.w);
    }
    __syncthreads();

    // per-row ||z||^2, sequential fp32 d-ascending (matches reference rounding)
    if (tid < BM) {
        float s = 0.0f;
        #pragma unroll
        for (int k = 0; k < DDIM; ++k) {
            float v = zDup[k * BM + tid].x;
            s = __fadd_rn(s, __fmul_rn(v, v));
        }
        zn[tid] = s;
    }
    CP_WAIT0();
    __syncthreads();

    float znr[4];
    #pragma unroll
    for (int i = 0; i < 4; ++i) znr[i] = zn[4 * ty + i];

    float mind[4];
    int   mini[4];
    #pragma unroll
    for (int i = 0; i < 4; ++i) { mind[i] = 3.402823466e38f; mini[i] = 0; }

    // ---- main loop over 8 code chunks of 128 ----
    for (int ch = 0; ch < NCH; ++ch) {
        const float* ek = eBuf + (ch & 1) * 8192;

        // prefetch next chunk into the other buffer
        if (ch + 1 < NCH) {
            float* dstf = eBuf + ((ch + 1) & 1) * 8192;
            const float* srcb = g_embT + (size_t)(ch + 1) * 8192;
            #pragma unroll
            for (int i = 0; i < 8; ++i) {
                int u = tid + i * 256;
                unsigned d = (unsigned)__cvta_generic_to_shared(dstf + u * 4);
                CP_ASYNC16(d, srcb + u * 4);
            }
            CP_COMMIT();
        }

        unsigned long long acc[4][4];
        #pragma unroll
        for (int i = 0; i < 4; ++i)
            #pragma unroll
            for (int p = 0; p < 4; ++p) acc[i][p] = 0ull;

        // dot products: k ascending, one packed accumulator per (row, code-pair)
        #pragma unroll 8
        for (int k = 0; k < DDIM; ++k) {
            ulonglong2 zd0 = *(const ulonglong2*)(zDup + k * BM + 4 * ty);      // rows 4ty,4ty+1 (dup)
            ulonglong2 zd1 = *(const ulonglong2*)(zDup + k * BM + 4 * ty + 2);  // rows 4ty+2,4ty+3
            ulonglong2 ea  = *(const ulonglong2*)(ek + k * BN + tx * 4);        // code pairs (0,1),(2,3)
            ulonglong2 eb  = *(const ulonglong2*)(ek + k * BN + 64 + tx * 4);   // code pairs (4,5),(6,7)

            FMA2(acc[0][0], zd0.x, ea.x); FMA2(acc[0][1], zd0.x, ea.y);
            FMA2(acc[0][2], zd0.x, eb.x); FMA2(acc[0][3], zd0.x, eb.y);
            FMA2(acc[1][0], zd0.y, ea.x); FMA2(acc[1][1], zd0.y, ea.y);
            FMA2(acc[1][2], zd0.y, eb.x); FMA2(acc[1][3], zd0.y, eb.y);
            FMA2(acc[2][0], zd1.x, ea.x); FMA2(acc[2][1], zd1.x, ea.y);
            FMA2(acc[2][2], zd1.x, eb.x); FMA2(acc[2][3], zd1.x, eb.y);
            FMA2(acc[3][0], zd1.y, ea.x); FMA2(acc[3][1], zd1.y, ea.y);
            FMA2(acc[3][2], zd1.y, eb.x); FMA2(acc[3][3], zd1.y, eb.y);
        }

        // dist = fma(dot, -2, znorm + enorm)  — -2*dot exact, single rounding,
        // identical to fadd((znorm+enorm), -2*dot). Codes visited ascending.
        int cbase = ch * BN + 8 * tx;
        #pragma unroll
        for (int p = 0; p < 4; ++p) {
            float en0 = __ldg(&g_enorm[cbase + 2 * p]);
            float en1 = __ldg(&g_enorm[cbase + 2 * p + 1]);
            #pragma unroll
            for (int i = 0; i < 4; ++i) {
                float lo = __uint_as_float((unsigned)(acc[i][p]));
                float hi = __uint_as_float((unsigned)(acc[i][p] >> 32));
                float d0 = __fmaf_rn(lo, -2.0f, __fadd_rn(znr[i], en0));
                float d1 = __fmaf_rn(hi, -2.0f, __fadd_rn(znr[i], en1));
                if (d0 < mind[i]) { mind[i] = d0; mini[i] = cbase + 2 * p; }
                if (d1 < mind[i]) { mind[i] = d1; mini[i] = cbase + 2 * p + 1; }
            }
        }

        if (ch + 1 < NCH) {
            CP_WAIT0();
            __syncthreads();
        }
    }

    // ---- argmin reduce across the 16 code-threads (tie-break: min index) ----
    #pragma unroll
    for (int i = 0; i < 4; ++i) {
        float d  = mind[i];
        int   ix = mini[i];
        #pragma unroll
        for (int m = 8; m >= 1; m >>= 1) {
            float od = __shfl_xor_sync(0xffffffffu, d,  m);
            int   oi = __shfl_xor_sync(0xffffffffu, ix, m);
            if (od < d || (od == d && oi < ix)) { d = od; ix = oi; }
        }
        if (tx == 0) idx_s[4 * ty + i] = ix;
    }
    __syncthreads();

    // ---- gather z_q = emb[idx], write idx, accumulate (z_q - z)^2 ----
    {
        int   r    = tid >> 2;     // row 0..63, 4 threads per row
        int   q    = tid & 3;      // quarter of headdim
        int   ix   = idx_s[r];
        int   grow = row0 + r;
        float psum = 0.0f;
        #pragma unroll
        for (int s4 = 0; s4 < 4; ++s4) {
            int d0 = q * 16 + s4 * 4;
            float4 e4 = *(const float4*)(emb + (size_t)ix * DDIM + d0);
            float zx = zDup[(d0 + 0) * BM + r].x;
            float zy = zDup[(d0 + 1) * BM + r].x;
            float zz = zDup[(d0 + 2) * BM + r].x;
            float zw = zDup[(d0 + 3) * BM + r].x;
            float dx = __fadd_rn(e4.x, -zx);
            float dy = __fadd_rn(e4.y, -zy);
            float dz = __fadd_rn(e4.z, -zz);
            float dw = __fadd_rn(e4.w, -zw);
            psum = __fmaf_rn(dx, dx, psum);
            psum = __fmaf_rn(dy, dy, psum);
            psum = __fmaf_rn(dz, dz, psum);
            psum = __fmaf_rn(dw, dw, psum);
            *(float4*)(out_zq + (size_t)grow * DDIM + d0) = e4;
        }
        if (q == 0) out_idx[grow] = (float)ix;
        red[tid] = psum;
    }
    __syncthreads();
    #pragma unroll
    for (int s = 128; s > 0; s >>= 1) {
        if (tid < s) red[tid] = __fadd_rn(red[tid], red[tid + s]);
        __syncthreads();
    }
    if (tid == 0) g_partial[blockIdx.x] = red[0];
}

// ---------------------------------------------------------------------------
// Deterministic loss reduction: loss = 1.25 * (global sq sum) / (T*D)
// ---------------------------------------------------------------------------
__global__ __launch_bounds__(256) void loss_kernel(float* __restrict__ out_loss) {
    __shared__ float s[256];
    int tid = threadIdx.x;
    float v = g_partial[tid];
    v = __fadd_rn(v, g_partial[tid + 256]);
    v = __fadd_rn(v, g_partial[tid + 512]);
    v = __fadd_rn(v, g_partial[tid + 768]);
    s[tid] = v;
    __syncthreads();
    #pragma unroll
    for (int t = 128; t > 0; t >>= 1) {
        if (tid < t) s[tid] = __fadd_rn(s[tid], s[tid + t]);
        __syncthreads();
    }
    if (tid == 0)
        out_loss[0] = 1.25f * (s[0] * (1.0f / 262144.0f));  // 1/(4096*64)
}

// ---------------------------------------------------------------------------
extern "C" void kernel_launch(void* const* d_in, const int* in_sizes, int n_in,
                              void* d_out, int out_size) {
    const float* a0 = (const float*)d_in[0];
    const float* a1 = (const float*)d_in[1];
    const float* z;
    const float* emb;
    if (in_sizes[0] == BT * DDIM) { z = a0; emb = a1; }
    else                          { z = a1; emb = a0; }

    float* out      = (float*)d_out;
    float* out_zq   = out;                                  // 4,194,304
    float* out_loss = out + (size_t)BT * DDIM;              // 1
    float* out_idx  = out + (size_t)BT * DDIM + 1;          // 65,536

    cudaFuncSetAttribute(vq_main, cudaFuncAttributeMaxDynamicSharedMemorySize,
                         SMEM_TOTAL);

    prep_kernel<<<KCODES / 128, 128>>>(emb);
    vq_main<<<BT / BM, 256, SMEM_TOTAL>>>(z, emb, out_zq, out_idx);
    loss_kernel<<<1, 256>>>(out_loss);
}

// round 11
// speedup vs baseline: 1.8099x; 1.8099x over previous
#include <cuda_runtime.h>
#include <cuda_bf16.h>
#include <cstdint>
#include <cstddef>

// Problem constants
#define BT      65536          // B*T rows
#define DDIM    64
#define KCODES  1024
#define BM      128            // rows per CTA
#define CHCODES 128            // codes per streamed chunk
#define NCH     (KCODES / CHCODES)   // 8
#define MARGIN  2.5e-3f        // sound screening window (see analysis)

// Dynamic smem layout (bytes)
#define ZPAD     68                          // fp32 row stride (272B, 16B-aligned)
#define SM_ZF    0                           // 128 x 68 f32        = 34816
#define SM_ZN    34816                       // 128 f32             =   512
#define SM_EB    (34816 + 512)               // 2 x 16384 (frag-packed bf16)
#define SM_EN    (SM_EB + 32768)             // 2 x 128 f32         =  1024
#define SM_IDX   (SM_EN + 1024)              // 128 int             =   512
#define SM_PD    (SM_IDX + 512)              // 128x2 f32 pair dists=  1024
#define SM_PI    (SM_PD + 1024)              // 128x2 int pair idx  =  1024
#define SM_RED   (SM_PI + 1024)              // 256 f32             =  1024
#define SMEM_TOTAL (SM_RED + 1024)           // 72704 B -> 2 CTAs/SM

__device__ float    g_enorm[KCODES];
__device__ unsigned g_embB[KCODES / 8 * 32 * 8];  // mma-fragment-packed bf16 (128KB)
__device__ float    g_partial[BT / BM];           // 512 per-block loss partials

#define CP_ASYNC16(dst_u32, src_ptr) \
    asm volatile("cp.async.ca.shared.global [%0], [%1], 16;" :: "r"(dst_u32), "l"(src_ptr))
#define CP_COMMIT()  asm volatile("cp.async.commit_group;")
#define CP_WAIT0()   asm volatile("cp.async.wait_group 0;" ::: "memory")

__device__ __forceinline__ unsigned pk_bf2(float a, float b) {
    unsigned short lo = __bfloat16_as_ushort(__float2bfloat16(a));
    unsigned short hi = __bfloat16_as_ushort(__float2bfloat16(b));
    return (unsigned)lo | ((unsigned)hi << 16);
}

__device__ __forceinline__ void mma_bf16(float c[4], const unsigned a[4],
                                         unsigned b0, unsigned b1) {
    asm volatile(
        "mma.sync.aligned.m16n8k16.row.col.f32.bf16.bf16.f32 "
        "{%0,%1,%2,%3}, {%4,%5,%6,%7}, {%8,%9}, {%0,%1,%2,%3};"
        : "+f"(c[0]), "+f"(c[1]), "+f"(c[2]), "+f"(c[3])
        : "r"(a[0]), "r"(a[1]), "r"(a[2]), "r"(a[3]), "r"(b0), "r"(b1));
}

// sorted best-4 insert (ascending dist); rare taken-path after warmup
__device__ __forceinline__ void ins4(float s, int ix, float* bd, int* bi) {
    if (s < bd[3]) {
        if (s < bd[1]) {
            if (s < bd[0]) {
                bd[3]=bd[2]; bi[3]=bi[2]; bd[2]=bd[1]; bi[2]=bi[1];
                bd[1]=bd[0]; bi[1]=bi[0]; bd[0]=s;     bi[0]=ix;
            } else {
                bd[3]=bd[2]; bi[3]=bi[2]; bd[2]=bd[1]; bi[2]=bi[1];
                bd[1]=s;     bi[1]=ix;
            }
        } else {
            if (s < bd[2]) { bd[3]=bd[2]; bi[3]=bi[2]; bd[2]=s; bi[2]=ix; }
            else           { bd[3]=s;     bi[3]=ix; }
        }
    }
}

// exact-phase dist: identical numerics to the R3 kernel (seq fp32 k-ascending
// dot; t = fadd(zn,en); dist = fma(dot,-2,t) == fadd(t,-2*dot) exactly)
__device__ __forceinline__ void exact_eval(const float* __restrict__ zrow,
                                           const float* __restrict__ emb,
                                           float zn, int ix,
                                           float& bD, int& bI) {
    const float4* e4 = (const float4*)(emb + (size_t)ix * DDIM);
    float acc = 0.0f;
    #pragma unroll
    for (int q = 0; q < 16; ++q) {
        float4 e = __ldg(&e4[q]);
        acc = __fmaf_rn(zrow[4*q+0], e.x, acc);
        acc = __fmaf_rn(zrow[4*q+1], e.y, acc);
        acc = __fmaf_rn(zrow[4*q+2], e.z, acc);
        acc = __fmaf_rn(zrow[4*q+3], e.w, acc);
    }
    float t = __fadd_rn(zn, __ldg(&g_enorm[ix]));
    float D = __fmaf_rn(acc, -2.0f, t);
    if (D < bD || (D == bD && ix < bI)) { bD = D; bI = ix; }
}

// ---------------------------------------------------------------------------
// Prep: enorm (sequential fp32, reference order) + fragment-packed bf16 emb.
// b-frag spec (m16n8k16, col-major B): lane l (g=l>>2, t=l&3), step ks:
//   b0 = {B[16ks+2t][n], B[16ks+2t+1][n]},  b1 = same with +8 on k.
// word(l, ks, h) = pack(emb[c][16ks+8h+2t], emb[c][16ks+8h+2t+1]), c = nf*8+g.
// ---------------------------------------------------------------------------
__global__ __launch_bounds__(128) void prep_kernel(const float* __restrict__ emb) {
    int c = blockIdx.x * 128 + threadIdx.x;     // grid=8 -> c in [0,1024)
    const float* e = emb + (size_t)c * DDIM;
    float v[DDIM];
    float s = 0.0f;
    #pragma unroll
    for (int q = 0; q < 16; ++q) {
        float4 t4 = *(const float4*)(e + q * 4);
        v[q*4+0] = t4.x; v[q*4+1] = t4.y; v[q*4+2] = t4.z; v[q*4+3] = t4.w;
        s = __fadd_rn(s, __fmul_rn(t4.x, t4.x));
        s = __fadd_rn(s, __fmul_rn(t4.y, t4.y));
        s = __fadd_rn(s, __fmul_rn(t4.z, t4.z));
        s = __fadd_rn(s, __fmul_rn(t4.w, t4.w));
    }
    g_enorm[c] = s;

    int nf = c >> 3;
    int g  = c & 7;
    #pragma unroll
    for (int t = 0; t < 4; ++t) {
        int lane = g * 4 + t;
        #pragma unroll
        for (int ks = 0; ks < 4; ++ks)
            #pragma unroll
            for (int h = 0; h < 2; ++h) {
                int k = 16 * ks + 8 * h + 2 * t;
                g_embB[((nf * 32 + lane) * 8) + ks * 2 + h] = pk_bf2(v[k], v[k+1]);
            }
    }
}

// ---------------------------------------------------------------------------
// Main VQ: bf16 mma screening (best-4/lane) + exact fp32 verify + gather/loss
// Warp layout: wm = warp&3 -> rows 32*wm..+31 (two m16 frags);
//              wn = warp>>2 -> code half (512 codes each).
// ---------------------------------------------------------------------------
__global__ __launch_bounds__(256, 2) void vq_main(const float* __restrict__ z,
                                                  const float* __restrict__ emb,
                                                  float* __restrict__ out_zq,
                                                  float* __restrict__ out_idx) {
    extern __shared__ char smem_raw[];
    float*    zF   = (float*)   (smem_raw + SM_ZF);    // [128][68]
    float*    znS  = (float*)   (smem_raw + SM_ZN);
    unsigned* eB   = (unsigned*)(smem_raw + SM_EB);    // 2 x 4096 words
    float*    enS  = (float*)   (smem_raw + SM_EN);    // 2 x 128
    int*      idxS = (int*)     (smem_raw + SM_IDX);
    float*    pD   = (float*)   (smem_raw + SM_PD);    // [128][2]
    int*      pI   = (int*)     (smem_raw + SM_PI);
    float*    red  = (float*)   (smem_raw + SM_RED);

    const int tid  = threadIdx.x;
    const int lane = tid & 31;
    const int warp = tid >> 5;
    const int g    = lane >> 2;
    const int t2   = (lane & 3) * 2;         // col / k offset 2t
    const int wm   = warp & 3;               // m-quadrant (32 rows)
    const int wn   = warp >> 2;              // code half
    const int R0   = wm * 32;
    const int row0 = blockIdx.x * BM;

    // ---- prologue cp.async: zF tile, emb chunk 0, enorm chunk 0 ----
    #pragma unroll
    for (int i = 0; i < 8; ++i) {            // 2048 x 16B  (z: 128 rows x 256B)
        int u = tid + i * 256;
        int r = u >> 4, seg = u & 15;
        unsigned d = (unsigned)__cvta_generic_to_shared(zF + r * ZPAD + seg * 4);
        CP_ASYNC16(d, z + (size_t)(row0 + r) * DDIM + seg * 4);
    }
    #pragma unroll
    for (int i = 0; i < 4; ++i) {            // 1024 x 16B  (emb chunk = 16KB)
        int u = tid + i * 256;
        unsigned d = (unsigned)__cvta_generic_to_shared(eB + u * 4);
        CP_ASYNC16(d, g_embB + u * 4);
    }
    if (tid < 32) {                          // enorm chunk = 512B
        unsigned d = (unsigned)__cvta_generic_to_shared(enS + tid * 4);
        CP_ASYNC16(d, g_enorm + tid * 4);
    }
    CP_COMMIT();
    CP_WAIT0();
    __syncthreads();

    // ---- per-row ||z||^2 (sequential fp32, reference order) ----
    if (tid < BM) {
        const float* zr = zF + tid * ZPAD;
        float s = 0.0f;
        #pragma unroll
        for (int k = 0; k < DDIM; ++k)
            s = __fadd_rn(s, __fmul_rn(zr[k], zr[k]));
        znS[tid] = s;
    }

    // ---- build A fragments (two m16 frags, bf16) from zF ----
    unsigned aF[2][4][4];
    #pragma unroll
    for (int m2 = 0; m2 < 2; ++m2) {
        int ra = R0 + 16 * m2 + g;
        #pragma unroll
        for (int ks = 0; ks < 4; ++ks) {
            int k = 16 * ks + t2;
            aF[m2][ks][0] = pk_bf2(zF[ra * ZPAD + k],           zF[ra * ZPAD + k + 1]);
            aF[m2][ks][1] = pk_bf2(zF[(ra+8) * ZPAD + k],       zF[(ra+8) * ZPAD + k + 1]);
            aF[m2][ks][2] = pk_bf2(zF[ra * ZPAD + k + 8],       zF[ra * ZPAD + k + 9]);
            aF[m2][ks][3] = pk_bf2(zF[(ra+8) * ZPAD + k + 8],   zF[(ra+8) * ZPAD + k + 9]);
        }
    }

    // per-lane best-4 for 4 owned rows: sets {R0+g, R0+8+g, R0+16+g, R0+24+g}
    float bd[4][4];
    int   bi[4][4];
    #pragma unroll
    for (int s = 0; s < 4; ++s)
        #pragma unroll
        for (int j = 0; j < 4; ++j) { bd[s][j] = 3.402823466e38f; bi[s][j] = 0; }

    // ---- chunk loop: 8 chunks of 128 codes; warp handles its 8 n-frags ----
    for (int ch = 0; ch < NCH; ++ch) {
        if (ch + 1 < NCH) {
            unsigned* dstb = eB + ((ch + 1) & 1) * 4096;
            const unsigned* srcb = g_embB + (size_t)(ch + 1) * 4096;
            #pragma unroll
            for (int i = 0; i < 4; ++i) {
                int u = tid + i * 256;
                unsigned d = (unsigned)__cvta_generic_to_shared(dstb + u * 4);
                CP_ASYNC16(d, srcb + u * 4);
            }
            if (tid < 32) {
                unsigned d = (unsigned)__cvta_generic_to_shared(
                    enS + ((ch + 1) & 1) * 128 + tid * 4);
                CP_ASYNC16(d, g_enorm + (ch + 1) * 128 + tid * 4);
            }
            CP_COMMIT();
        }

        const unsigned* ebuf = eB  + (ch & 1) * 4096;
        const float*    ebn  = enS + (ch & 1) * 128;

        #pragma unroll
        for (int i = 0; i < 8; ++i) {
            int nf_l  = 8 * wn + i;
            int cbase = ch * CHCODES + nf_l * 8;

            const uint4* bp = (const uint4*)(ebuf + (nf_l * 32 + lane) * 8);
            uint4 bA = bp[0];      // ks0:{b0,b1}=x,y  ks1:{b0,b1}=z,w
            uint4 bB = bp[1];      // ks2, ks3
            float2 en2 = *(const float2*)(ebn + nf_l * 8 + t2);

            float c0[4] = {0.f, 0.f, 0.f, 0.f};
            float c1[4] = {0.f, 0.f, 0.f, 0.f};
            mma_bf16(c0, aF[0][0], bA.x, bA.y);  mma_bf16(c1, aF[1][0], bA.x, bA.y);
            mma_bf16(c0, aF[0][1], bA.z, bA.w);  mma_bf16(c1, aF[1][1], bA.z, bA.w);
            mma_bf16(c0, aF[0][2], bB.x, bB.y);  mma_bf16(c1, aF[1][2], bB.x, bB.y);
            mma_bf16(c0, aF[0][3], bB.z, bB.w);  mma_bf16(c1, aF[1][3], bB.z, bB.w);

            int i0 = cbase + t2, i1 = i0 + 1;
            ins4(__fmaf_rn(c0[0], -2.0f, en2.x), i0, bd[0], bi[0]);
            ins4(__fmaf_rn(c0[1], -2.0f, en2.y), i1, bd[0], bi[0]);
            ins4(__fmaf_rn(c0[2], -2.0f, en2.x), i0, bd[1], bi[1]);
            ins4(__fmaf_rn(c0[3], -2.0f, en2.y), i1, bd[1], bi[1]);
            ins4(__fmaf_rn(c1[0], -2.0f, en2.x), i0, bd[2], bi[2]);
            ins4(__fmaf_rn(c1[1], -2.0f, en2.y), i1, bd[2], bi[2]);
            ins4(__fmaf_rn(c1[2], -2.0f, en2.x), i0, bd[3], bi[3]);
            ins4(__fmaf_rn(c1[3], -2.0f, en2.y), i1, bd[3], bi[3]);
        }

        if (ch + 1 < NCH) {
            CP_WAIT0();
            __syncthreads();
        }
    }

    // ---- phase 2: exact verify of candidates within MARGIN of quad min ----
    #pragma unroll
    for (int s = 0; s < 4; ++s) {
        int rloc = R0 + ((s & 1) ? 8 : 0) + ((s >> 1) ? 16 : 0) + g;
        float gm = bd[s][0];
        gm = fminf(gm, __shfl_xor_sync(0xffffffffu, gm, 1));
        gm = fminf(gm, __shfl_xor_sync(0xffffffffu, gm, 2));
        float thr = gm + MARGIN;

        float bD = 3.402823466e38f;
        int   bI = 0x7fffffff;
        float zn = znS[rloc];
        const float* zrow = zF + rloc * ZPAD;
        if (bd[s][0] <= thr) exact_eval(zrow, emb, zn, bi[s][0], bD, bI);
        if (bd[s][1] <= thr) exact_eval(zrow, emb, zn, bi[s][1], bD, bI);
        if (bd[s][2] <= thr) exact_eval(zrow, emb, zn, bi[s][2], bD, bI);
        if (bd[s][3] <= thr) exact_eval(zrow, emb, zn, bi[s][3], bD, bI);

        // lexicographic (dist, idx) quad reduce
        #pragma unroll
        for (int m = 1; m <= 2; m <<= 1) {
            float oD = __shfl_xor_sync(0xffffffffu, bD, m);
            int   oI = __shfl_xor_sync(0xffffffffu, bI, m);
            if (oD < bD || (oD == bD && oI < bI)) { bD = oD; bI = oI; }
        }
        if ((lane & 3) == 0) { pD[rloc * 2 + wn] = bD; pI[rloc * 2 + wn] = bI; }
    }
    __syncthreads();

    // merge the two code-halves per row
    if (tid < BM) {
        float D0 = pD[tid * 2], D1 = pD[tid * 2 + 1];
        int   I0 = pI[tid * 2], I1 = pI[tid * 2 + 1];
        idxS[tid] = (D1 < D0 || (D1 == D0 && I1 < I0)) ? I1 : I0;
    }
    __syncthreads();

    // ---- gather z_q = emb[idx], write idx, accumulate (z_q - z)^2 ----
    {
        int   r    = tid >> 1;                 // row 0..127, 2 threads per row
        int   q    = tid & 1;                  // half of headdim
        int   ix   = idxS[r];
        int   grow = row0 + r;
        float psum = 0.0f;
        #pragma unroll
        for (int s4 = 0; s4 < 8; ++s4) {
            int d0 = q * 32 + s4 * 4;
            float4 e4 = *(const float4*)(emb + (size_t)ix * DDIM + d0);
            float4 z4 = *(const float4*)(zF + r * ZPAD + d0);
            float dx = __fadd_rn(e4.x, -z4.x);
            float dy = __fadd_rn(e4.y, -z4.y);
            float dz = __fadd_rn(e4.z, -z4.z);
            float dw = __fadd_rn(e4.w, -z4.w);
            psum = __fmaf_rn(dx, dx, psum);
            psum = __fmaf_rn(dy, dy, psum);
            psum = __fmaf_rn(dz, dz, psum);
            psum = __fmaf_rn(dw, dw, psum);
            *(float4*)(out_zq + (size_t)grow * DDIM + d0) = e4;
        }
        if (q == 0) out_idx[grow] = (float)ix;
        red[tid] = psum;
    }
    __syncthreads();
    #pragma unroll
    for (int s = 128; s > 0; s >>= 1) {
        if (tid < s) red[tid] = __fadd_rn(red[tid], red[tid + s]);
        __syncthreads();
    }
    if (tid == 0) g_partial[blockIdx.x] = red[0];
}

// ---------------------------------------------------------------------------
// Deterministic loss reduction: loss = 1.25 * (global sq sum) / (T*D)
// ---------------------------------------------------------------------------
__global__ __launch_bounds__(256) void loss_kernel(float* __restrict__ out_loss) {
    __shared__ float s[256];
    int tid = threadIdx.x;
    float v = __fadd_rn(g_partial[tid], g_partial[tid + 256]);
    s[tid] = v;
    __syncthreads();
    #pragma unroll
    for (int t = 128; t > 0; t >>= 1) {
        if (tid < t) s[tid] = __fadd_rn(s[tid], s[tid + t]);
        __syncthreads();
    }
    if (tid == 0)
        out_loss[0] = 1.25f * (s[0] * (1.0f / 262144.0f));  // 1/(4096*64)
}

// ---------------------------------------------------------------------------
extern "C" void kernel_launch(void* const* d_in, const int* in_sizes, int n_in,
                              void* d_out, int out_size) {
    const float* a0 = (const float*)d_in[0];
    const float* a1 = (const float*)d_in[1];
    const float* z;
    const float* emb;
    if (in_sizes[0] == BT * DDIM) { z = a0; emb = a1; }
    else                          { z = a1; emb = a0; }

    float* out      = (float*)d_out;
    float* out_zq   = out;                                  // 4,194,304
    float* out_loss = out + (size_t)BT * DDIM;              // 1
    float* out_idx  = out + (size_t)BT * DDIM + 1;          // 65,536

    cudaFuncSetAttribute(vq_main, cudaFuncAttributeMaxDynamicSharedMemorySize,
                         SMEM_TOTAL);

    prep_kernel<<<KCODES / 128, 128>>>(emb);
    vq_main<<<BT / BM, 256, SMEM_TOTAL>>>(z, emb, out_zq, out_idx);
    loss_kernel<<<1, 256>>>(out_loss);
}

// round 12
// speedup vs baseline: 1.8164x; 1.0036x over previous
#include <cuda_runtime.h>
#include <cuda_bf16.h>
#include <cstdint>
#include <cstddef>

// Problem constants
#define BT      65536          // B*T rows
#define DDIM    64
#define KCODES  1024
#define BM      128            // rows per CTA
#define CHCODES 128            // codes per streamed chunk
#define NCH     (KCODES / CHCODES)   // 8
#define MARGIN  2.5e-3f        // sound screening window (see analysis)

// Dynamic smem layout (bytes)
#define ZPAD     68                          // fp32 row stride (272B, 16B-aligned)
#define SM_ZF    0                           // 128 x 68 f32        = 34816
#define SM_ZN    34816                       // 128 f32             =   512
#define SM_EB    (34816 + 512)               // 2 x 16384 (frag-packed bf16)
#define SM_EN    (SM_EB + 32768)             // 2 x 128 f32         =  1024
#define SM_IDX   (SM_EN + 1024)              // 128 int             =   512
#define SM_PD    (SM_IDX + 512)              // 128x2 f32 pair dists=  1024
#define SM_PI    (SM_PD + 1024)              // 128x2 int pair idx  =  1024
#define SM_RED   (SM_PI + 1024)              // 256 f32             =  1024
#define SMEM_TOTAL (SM_RED + 1024)           // 72704 B -> 2 CTAs/SM

__device__ float    g_enorm[KCODES];
__device__ unsigned g_embB[KCODES / 8 * 32 * 8];  // mma-fragment-packed bf16 (128KB)
__device__ float    g_partial[BT / BM];           // 512 per-block loss partials

#define CP_ASYNC16(dst_u32, src_ptr) \
    asm volatile("cp.async.ca.shared.global [%0], [%1], 16;" :: "r"(dst_u32), "l"(src_ptr))
#define CP_COMMIT()  asm volatile("cp.async.commit_group;")
#define CP_WAIT0()   asm volatile("cp.async.wait_group 0;" ::: "memory")

__device__ __forceinline__ unsigned pk_bf2(float a, float b) {
    unsigned short lo = __bfloat16_as_ushort(__float2bfloat16(a));
    unsigned short hi = __bfloat16_as_ushort(__float2bfloat16(b));
    return (unsigned)lo | ((unsigned)hi << 16);
}

__device__ __forceinline__ void mma_bf16(float c[4], const unsigned a[4],
                                         unsigned b0, unsigned b1) {
    asm volatile(
        "mma.sync.aligned.m16n8k16.row.col.f32.bf16.bf16.f32 "
        "{%0,%1,%2,%3}, {%4,%5,%6,%7}, {%8,%9}, {%0,%1,%2,%3};"
        : "+f"(c[0]), "+f"(c[1]), "+f"(c[2]), "+f"(c[3])
        : "r"(a[0]), "r"(a[1]), "r"(a[2]), "r"(a[3]), "r"(b0), "r"(b1));
}

// sorted best-4 insert (ascending dist); rare taken-path after warmup
__device__ __forceinline__ void ins4(float s, int ix, float* bd, int* bi) {
    if (s < bd[3]) {
        if (s < bd[1]) {
            if (s < bd[0]) {
                bd[3]=bd[2]; bi[3]=bi[2]; bd[2]=bd[1]; bi[2]=bi[1];
                bd[1]=bd[0]; bi[1]=bi[0]; bd[0]=s;     bi[0]=ix;
            } else {
                bd[3]=bd[2]; bi[3]=bi[2]; bd[2]=bd[1]; bi[2]=bi[1];
                bd[1]=s;     bi[1]=ix;
            }
        } else {
            if (s < bd[2]) { bd[3]=bd[2]; bi[3]=bi[2]; bd[2]=s; bi[2]=ix; }
            else           { bd[3]=s;     bi[3]=ix; }
        }
    }
}

// exact-phase dist: identical numerics to the R3 kernel (seq fp32 k-ascending
// dot; t = fadd(zn,en); dist = fma(dot,-2,t) == fadd(t,-2*dot) exactly)
__device__ __forceinline__ void exact_eval(const float* __restrict__ zrow,
                                           const float* __restrict__ emb,
                                           float zn, int ix,
                                           float& bD, int& bI) {
    const float4* e4 = (const float4*)(emb + (size_t)ix * DDIM);
    float acc = 0.0f;
    #pragma unroll
    for (int q = 0; q < 16; ++q) {
        float4 e = __ldg(&e4[q]);
        acc = __fmaf_rn(zrow[4*q+0], e.x, acc);
        acc = __fmaf_rn(zrow[4*q+1], e.y, acc);
        acc = __fmaf_rn(zrow[4*q+2], e.z, acc);
        acc = __fmaf_rn(zrow[4*q+3], e.w, acc);
    }
    float t = __fadd_rn(zn, __ldg(&g_enorm[ix]));
    float D = __fmaf_rn(acc, -2.0f, t);
    if (D < bD || (D == bD && ix < bI)) { bD = D; bI = ix; }
}

// ---------------------------------------------------------------------------
// Prep: enorm (sequential fp32, reference order) + fragment-packed bf16 emb.
// b-frag spec (m16n8k16, col-major B): lane l (g=l>>2, t=l&3), step ks:
//   b0 = {B[16ks+2t][n], B[16ks+2t+1][n]},  b1 = same with +8 on k.
// word(l, ks, h) = pack(emb[c][16ks+8h+2t], emb[c][16ks+8h+2t+1]), c = nf*8+g.
// ---------------------------------------------------------------------------
__global__ __launch_bounds__(128) void prep_kernel(const float* __restrict__ emb) {
    int c = blockIdx.x * 128 + threadIdx.x;     // grid=8 -> c in [0,1024)
    const float* e = emb + (size_t)c * DDIM;
    float v[DDIM];
    float s = 0.0f;
    #pragma unroll
    for (int q = 0; q < 16; ++q) {
        float4 t4 = *(const float4*)(e + q * 4);
        v[q*4+0] = t4.x; v[q*4+1] = t4.y; v[q*4+2] = t4.z; v[q*4+3] = t4.w;
        s = __fadd_rn(s, __fmul_rn(t4.x, t4.x));
        s = __fadd_rn(s, __fmul_rn(t4.y, t4.y));
        s = __fadd_rn(s, __fmul_rn(t4.z, t4.z));
        s = __fadd_rn(s, __fmul_rn(t4.w, t4.w));
    }
    g_enorm[c] = s;

    int nf = c >> 3;
    int g  = c & 7;
    #pragma unroll
    for (int t = 0; t < 4; ++t) {
        int lane = g * 4 + t;
        #pragma unroll
        for (int ks = 0; ks < 4; ++ks)
            #pragma unroll
            for (int h = 0; h < 2; ++h) {
                int k = 16 * ks + 8 * h + 2 * t;
                g_embB[((nf * 32 + lane) * 8) + ks * 2 + h] = pk_bf2(v[k], v[k+1]);
            }
    }
}

// ---------------------------------------------------------------------------
// Main VQ: bf16 mma screening (best-4/lane) + exact fp32 verify + gather/loss
// Warp layout: wm = warp&3 -> rows 32*wm..+31 (two m16 frags);
//              wn = warp>>2 -> code half (512 codes each).
// ---------------------------------------------------------------------------
__global__ __launch_bounds__(256, 2) void vq_main(const float* __restrict__ z,
                                                  const float* __restrict__ emb,
                                                  float* __restrict__ out_zq,
                                                  float* __restrict__ out_idx) {
    extern __shared__ char smem_raw[];
    float*    zF   = (float*)   (smem_raw + SM_ZF);    // [128][68]
    float*    znS  = (float*)   (smem_raw + SM_ZN);
    unsigned* eB   = (unsigned*)(smem_raw + SM_EB);    // 2 x 4096 words
    float*    enS  = (float*)   (smem_raw + SM_EN);    // 2 x 128
    int*      idxS = (int*)     (smem_raw + SM_IDX);
    float*    pD   = (float*)   (smem_raw + SM_PD);    // [128][2]
    int*      pI   = (int*)     (smem_raw + SM_PI);
    float*    red  = (float*)   (smem_raw + SM_RED);

    const int tid  = threadIdx.x;
    const int lane = tid & 31;
    const int warp = tid >> 5;
    const int g    = lane >> 2;
    const int t2   = (lane & 3) * 2;         // col / k offset 2t
    const int wm   = warp & 3;               // m-quadrant (32 rows)
    const int wn   = warp >> 2;              // code half
    const int R0   = wm * 32;
    const int row0 = blockIdx.x * BM;

    // ---- prologue cp.async: zF tile, emb chunk 0, enorm chunk 0 ----
    #pragma unroll
    for (int i = 0; i < 8; ++i) {            // 2048 x 16B  (z: 128 rows x 256B)
        int u = tid + i * 256;
        int r = u >> 4, seg = u & 15;
        unsigned d = (unsigned)__cvta_generic_to_shared(zF + r * ZPAD + seg * 4);
        CP_ASYNC16(d, z + (size_t)(row0 + r) * DDIM + seg * 4);
    }
    #pragma unroll
    for (int i = 0; i < 4; ++i) {            // 1024 x 16B  (emb chunk = 16KB)
        int u = tid + i * 256;
        unsigned d = (unsigned)__cvta_generic_to_shared(eB + u * 4);
        CP_ASYNC16(d, g_embB + u * 4);
    }
    if (tid < 32) {                          // enorm chunk = 512B
        unsigned d = (unsigned)__cvta_generic_to_shared(enS + tid * 4);
        CP_ASYNC16(d, g_enorm + tid * 4);
    }
    CP_COMMIT();
    CP_WAIT0();
    __syncthreads();

    // ---- per-row ||z||^2 (sequential fp32, reference order) ----
    if (tid < BM) {
        const float* zr = zF + tid * ZPAD;
        float s = 0.0f;
        #pragma unroll
        for (int k = 0; k < DDIM; ++k)
            s = __fadd_rn(s, __fmul_rn(zr[k], zr[k]));
        znS[tid] = s;
    }

    // ---- build A fragments (two m16 frags, bf16) from zF ----
    unsigned aF[2][4][4];
    #pragma unroll
    for (int m2 = 0; m2 < 2; ++m2) {
        int ra = R0 + 16 * m2 + g;
        #pragma unroll
        for (int ks = 0; ks < 4; ++ks) {
            int k = 16 * ks + t2;
            aF[m2][ks][0] = pk_bf2(zF[ra * ZPAD + k],           zF[ra * ZPAD + k + 1]);
            aF[m2][ks][1] = pk_bf2(zF[(ra+8) * ZPAD + k],       zF[(ra+8) * ZPAD + k + 1]);
            aF[m2][ks][2] = pk_bf2(zF[ra * ZPAD + k + 8],       zF[ra * ZPAD + k + 9]);
            aF[m2][ks][3] = pk_bf2(zF[(ra+8) * ZPAD + k + 8],   zF[(ra+8) * ZPAD + k + 9]);
        }
    }

    // per-lane best-4 for 4 owned rows: sets {R0+g, R0+8+g, R0+16+g, R0+24+g}
    float bd[4][4];
    int   bi[4][4];
    #pragma unroll
    for (int s = 0; s < 4; ++s)
        #pragma unroll
        for (int j = 0; j < 4; ++j) { bd[s][j] = 3.402823466e38f; bi[s][j] = 0; }

    // ---- chunk loop: 8 chunks of 128 codes; warp handles its 8 n-frags ----
    for (int ch = 0; ch < NCH; ++ch) {
        if (ch + 1 < NCH) {
            unsigned* dstb = eB + ((ch + 1) & 1) * 4096;
            const unsigned* srcb = g_embB + (size_t)(ch + 1) * 4096;
            #pragma unroll
            for (int i = 0; i < 4; ++i) {
                int u = tid + i * 256;
                unsigned d = (unsigned)__cvta_generic_to_shared(dstb + u * 4);
                CP_ASYNC16(d, srcb + u * 4);
            }
            if (tid < 32) {
                unsigned d = (unsigned)__cvta_generic_to_shared(
                    enS + ((ch + 1) & 1) * 128 + tid * 4);
                CP_ASYNC16(d, g_enorm + (ch + 1) * 128 + tid * 4);
            }
            CP_COMMIT();
        }

        const unsigned* ebuf = eB  + (ch & 1) * 4096;
        const float*    ebn  = enS + (ch & 1) * 128;

        #pragma unroll
        for (int i = 0; i < 8; ++i) {
            int nf_l  = 8 * wn + i;
            int cbase = ch * CHCODES + nf_l * 8;

            const uint4* bp = (const uint4*)(ebuf + (nf_l * 32 + lane) * 8);
            uint4 bA = bp[0];      // ks0:{b0,b1}=x,y  ks1:{b0,b1}=z,w
            uint4 bB = bp[1];      // ks2, ks3
            float2 en2 = *(const float2*)(ebn + nf_l * 8 + t2);

            float c0[4] = {0.f, 0.f, 0.f, 0.f};
            float c1[4] = {0.f, 0.f, 0.f, 0.f};
            mma_bf16(c0, aF[0][0], bA.x, bA.y);  mma_bf16(c1, aF[1][0], bA.x, bA.y);
            mma_bf16(c0, aF[0][1], bA.z, bA.w);  mma_bf16(c1, aF[1][1], bA.z, bA.w);
            mma_bf16(c0, aF[0][2], bB.x, bB.y);  mma_bf16(c1, aF[1][2], bB.x, bB.y);
            mma_bf16(c0, aF[0][3], bB.z, bB.w);  mma_bf16(c1, aF[1][3], bB.z, bB.w);

            int i0 = cbase + t2, i1 = i0 + 1;
            ins4(__fmaf_rn(c0[0], -2.0f, en2.x), i0, bd[0], bi[0]);
            ins4(__fmaf_rn(c0[1], -2.0f, en2.y), i1, bd[0], bi[0]);
            ins4(__fmaf_rn(c0[2], -2.0f, en2.x), i0, bd[1], bi[1]);
            ins4(__fmaf_rn(c0[3], -2.0f, en2.y), i1, bd[1], bi[1]);
            ins4(__fmaf_rn(c1[0], -2.0f, en2.x), i0, bd[2], bi[2]);
            ins4(__fmaf_rn(c1[1], -2.0f, en2.y), i1, bd[2], bi[2]);
            ins4(__fmaf_rn(c1[2], -2.0f, en2.x), i0, bd[3], bi[3]);
            ins4(__fmaf_rn(c1[3], -2.0f, en2.y), i1, bd[3], bi[3]);
        }

        if (ch + 1 < NCH) {
            CP_WAIT0();
            __syncthreads();
        }
    }

    // ---- phase 2: exact verify of candidates within MARGIN of quad min ----
    #pragma unroll
    for (int s = 0; s < 4; ++s) {
        int rloc = R0 + ((s & 1) ? 8 : 0) + ((s >> 1) ? 16 : 0) + g;
        float gm = bd[s][0];
        gm = fminf(gm, __shfl_xor_sync(0xffffffffu, gm, 1));
        gm = fminf(gm, __shfl_xor_sync(0xffffffffu, gm, 2));
        float thr = gm + MARGIN;

        float bD = 3.402823466e38f;
        int   bI = 0x7fffffff;
        float zn = znS[rloc];
        const float* zrow = zF + rloc * ZPAD;
        if (bd[s][0] <= thr) exact_eval(zrow, emb, zn, bi[s][0], bD, bI);
        if (bd[s][1] <= thr) exact_eval(zrow, emb, zn, bi[s][1], bD, bI);
        if (bd[s][2] <= thr) exact_eval(zrow, emb, zn, bi[s][2], bD, bI);
        if (bd[s][3] <= thr) exact_eval(zrow, emb, zn, bi[s][3], bD, bI);

        // lexicographic (dist, idx) quad reduce
        #pragma unroll
        for (int m = 1; m <= 2; m <<= 1) {
            float oD = __shfl_xor_sync(0xffffffffu, bD, m);
            int   oI = __shfl_xor_sync(0xffffffffu, bI, m);
            if (oD < bD || (oD == bD && oI < bI)) { bD = oD; bI = oI; }
        }
        if ((lane & 3) == 0) { pD[rloc * 2 + wn] = bD; pI[rloc * 2 + wn] = bI; }
    }
    __syncthreads();

    // merge the two code-halves per row
    if (tid < BM) {
        float D0 = pD[tid * 2], D1 = pD[tid * 2 + 1];
        int   I0 = pI[tid * 2], I1 = pI[tid * 2 + 1];
        idxS[tid] = (D1 < D0 || (D1 == D0 && I1 < I0)) ? I1 : I0;
    }
    __syncthreads();

    // ---- gather z_q = emb[idx], write idx, accumulate (z_q - z)^2 ----
    {
        int   r    = tid >> 1;                 // row 0..127, 2 threads per row
        int   q    = tid & 1;                  // half of headdim
        int   ix   = idxS[r];
        int   grow = row0 + r;
        float psum = 0.0f;
        #pragma unroll
        for (int s4 = 0; s4 < 8; ++s4) {
            int d0 = q * 32 + s4 * 4;
            float4 e4 = *(const float4*)(emb + (size_t)ix * DDIM + d0);
            float4 z4 = *(const float4*)(zF + r * ZPAD + d0);
            float dx = __fadd_rn(e4.x, -z4.x);
            float dy = __fadd_rn(e4.y, -z4.y);
            float dz = __fadd_rn(e4.z, -z4.z);
            float dw = __fadd_rn(e4.w, -z4.w);
            psum = __fmaf_rn(dx, dx, psum);
            psum = __fmaf_rn(dy, dy, psum);
            psum = __fmaf_rn(dz, dz, psum);
            psum = __fmaf_rn(dw, dw, psum);
            *(float4*)(out_zq + (size_t)grow * DDIM + d0) = e4;
        }
        if (q == 0) out_idx[grow] = (float)ix;
        red[tid] = psum;
    }
    __syncthreads();
    #pragma unroll
    for (int s = 128; s > 0; s >>= 1) {
        if (tid < s) red[tid] = __fadd_rn(red[tid], red[tid + s]);
        __syncthreads();
    }
    if (tid == 0) g_partial[blockIdx.x] = red[0];
}

// ---------------------------------------------------------------------------
// Deterministic loss reduction: loss = 1.25 * (global sq sum) / (T*D)
// ---------------------------------------------------------------------------
__global__ __launch_bounds__(256) void loss_kernel(float* __restrict__ out_loss) {
    __shared__ float s[256];
    int tid = threadIdx.x;
    float v = __fadd_rn(g_partial[tid], g_partial[tid + 256]);
    s[tid] = v;
    __syncthreads();
    #pragma unroll
    for (int t = 128; t > 0; t >>= 1) {
        if (tid < t) s[tid] = __fadd_rn(s[tid], s[tid + t]);
        __syncthreads();
    }
    if (tid == 0)
        out_loss[0] = 1.25f * (s[0] * (1.0f / 262144.0f));  // 1/(4096*64)
}

// ---------------------------------------------------------------------------
extern "C" void kernel_launch(void* const* d_in, const int* in_sizes, int n_in,
                              void* d_out, int out_size) {
    const float* a0 = (const float*)d_in[0];
    const float* a1 = (const float*)d_in[1];
    const float* z;
    const float* emb;
    if (in_sizes[0] == BT * DDIM) { z = a0; emb = a1; }
    else                          { z = a1; emb = a0; }

    float* out      = (float*)d_out;
    float* out_zq   = out;                                  // 4,194,304
    float* out_loss = out + (size_t)BT * DDIM;              // 1
    float* out_idx  = out + (size_t)BT * DDIM + 1;          // 65,536

    cudaFuncSetAttribute(vq_main, cudaFuncAttributeMaxDynamicSharedMemorySize,
                         SMEM_TOTAL);

    prep_kernel<<<KCODES / 128, 128>>>(emb);
    vq_main<<<BT / BM, 256, SMEM_TOTAL>>>(z, emb, out_zq, out_idx);
    loss_kernel<<<1, 256>>>(out_loss);
}

// round 17
// speedup vs baseline: 1.8380x; 1.0119x over previous
#include <cuda_runtime.h>
#include <cuda_bf16.h>
#include <cstdint>
#include <cstddef>

// Problem constants
#define BT      65536          // B*T rows
#define DDIM    64
#define KCODES  1024
#define BM      128            // rows per CTA
#define CHCODES 128            // codes per streamed chunk
#define NCH     (KCODES / CHCODES)   // 8
#define MARGIN  2.5e-3f        // sound screening window (see analysis)

// Dynamic smem layout (bytes)
#define ZPAD     68                          // fp32 row stride (272B, 16B-aligned)
#define SM_ZF    0                           // 128 x 68 f32        = 34816
#define SM_ZN    34816                       // 128 f32             =   512
#define SM_EB    (34816 + 512)               // 2 x 16384 (frag-packed bf16)
#define SM_EN    (SM_EB + 32768)             // 2 x 128 f32         =  1024
#define SM_IDX   (SM_EN + 1024)              // 128 int             =   512
#define SM_PD    (SM_IDX + 512)              // 128x2 f32 pair dists=  1024
#define SM_PI    (SM_PD + 1024)              // 128x2 int pair idx  =  1024
#define SM_RED   (SM_PI + 1024)              // 256 f32             =  1024
#define SMEM_TOTAL (SM_RED + 1024)           // 72704 B -> 2 CTAs/SM

__device__ float    g_enorm[KCODES];
__device__ unsigned g_embB[KCODES / 8 * 32 * 8];  // mma-fragment-packed bf16 (128KB)
__device__ float    g_partial[BT / BM];           // 512 per-block loss partials

#define CP_ASYNC16(dst_u32, src_ptr) \
    asm volatile("cp.async.ca.shared.global [%0], [%1], 16;" :: "r"(dst_u32), "l"(src_ptr))
#define CP_COMMIT()  asm volatile("cp.async.commit_group;")
#define CP_WAIT0()   asm volatile("cp.async.wait_group 0;" ::: "memory")

__device__ __forceinline__ unsigned pk_bf2(float a, float b) {
    unsigned short lo = __bfloat16_as_ushort(__float2bfloat16(a));
    unsigned short hi = __bfloat16_as_ushort(__float2bfloat16(b));
    return (unsigned)lo | ((unsigned)hi << 16);
}

__device__ __forceinline__ void mma_bf16(float c[4], const unsigned a[4],
                                         unsigned b0, unsigned b1) {
    asm volatile(
        "mma.sync.aligned.m16n8k16.row.col.f32.bf16.bf16.f32 "
        "{%0,%1,%2,%3}, {%4,%5,%6,%7}, {%8,%9}, {%0,%1,%2,%3};"
        : "+f"(c[0]), "+f"(c[1]), "+f"(c[2]), "+f"(c[3])
        : "r"(a[0]), "r"(a[1]), "r"(a[2]), "r"(a[3]), "r"(b0), "r"(b1));
}

// sorted best-4 insert (ascending dist); rare taken-path after warmup
__device__ __forceinline__ void ins4(float s, int ix, float* bd, int* bi) {
    if (s < bd[3]) {
        if (s < bd[1]) {
            if (s < bd[0]) {
                bd[3]=bd[2]; bi[3]=bi[2]; bd[2]=bd[1]; bi[2]=bi[1];
                bd[1]=bd[0]; bi[1]=bi[0]; bd[0]=s;     bi[0]=ix;
            } else {
                bd[3]=bd[2]; bi[3]=bi[2]; bd[2]=bd[1]; bi[2]=bi[1];
                bd[1]=s;     bi[1]=ix;
            }
        } else {
            if (s < bd[2]) { bd[3]=bd[2]; bi[3]=bi[2]; bd[2]=s; bi[2]=ix; }
            else           { bd[3]=s;     bi[3]=ix; }
        }
    }
}

// exact-phase dist: identical numerics to the R3 kernel (seq fp32 k-ascending
// dot; t = fadd(zn,en); dist = fma(dot,-2,t) == fadd(t,-2*dot) exactly)
__device__ __forceinline__ void exact_eval(const float* __restrict__ zrow,
                                           const float* __restrict__ emb,
                                           float zn, int ix,
                                           float& bD, int& bI) {
    const float4* e4 = (const float4*)(emb + (size_t)ix * DDIM);
    float acc = 0.0f;
    #pragma unroll
    for (int q = 0; q < 16; ++q) {
        float4 e = __ldg(&e4[q]);
        acc = __fmaf_rn(zrow[4*q+0], e.x, acc);
        acc = __fmaf_rn(zrow[4*q+1], e.y, acc);
        acc = __fmaf_rn(zrow[4*q+2], e.z, acc);
        acc = __fmaf_rn(zrow[4*q+3], e.w, acc);
    }
    float t = __fadd_rn(zn, __ldg(&g_enorm[ix]));
    float D = __fmaf_rn(acc, -2.0f, t);
    if (D < bD || (D == bD && ix < bI)) { bD = D; bI = ix; }
}

// ---------------------------------------------------------------------------
// Prep: enorm (sequential fp32, reference order) + fragment-packed bf16 emb.
// b-frag spec (m16n8k16, col-major B): lane l (g=l>>2, t=l&3), step ks:
//   b0 = {B[16ks+2t][n], B[16ks+2t+1][n]},  b1 = same with +8 on k.
// word(l, ks, h) = pack(emb[c][16ks+8h+2t], emb[c][16ks+8h+2t+1]), c = nf*8+g.
// ---------------------------------------------------------------------------
__global__ __launch_bounds__(128) void prep_kernel(const float* __restrict__ emb) {
    int c = blockIdx.x * 128 + threadIdx.x;     // grid=8 -> c in [0,1024)
    const float* e = emb + (size_t)c * DDIM;
    float v[DDIM];
    float s = 0.0f;
    #pragma unroll
    for (int q = 0; q < 16; ++q) {
        float4 t4 = *(const float4*)(e + q * 4);
        v[q*4+0] = t4.x; v[q*4+1] = t4.y; v[q*4+2] = t4.z; v[q*4+3] = t4.w;
        s = __fadd_rn(s, __fmul_rn(t4.x, t4.x));
        s = __fadd_rn(s, __fmul_rn(t4.y, t4.y));
        s = __fadd_rn(s, __fmul_rn(t4.z, t4.z));
        s = __fadd_rn(s, __fmul_rn(t4.w, t4.w));
    }
    g_enorm[c] = s;

    int nf = c >> 3;
    int g  = c & 7;
    #pragma unroll
    for (int t = 0; t < 4; ++t) {
        int lane = g * 4 + t;
        #pragma unroll
        for (int ks = 0; ks < 4; ++ks)
            #pragma unroll
            for (int h = 0; h < 2; ++h) {
                int k = 16 * ks + 8 * h + 2 * t;
                g_embB[((nf * 32 + lane) * 8) + ks * 2 + h] = pk_bf2(v[k], v[k+1]);
            }
    }
}

// ---------------------------------------------------------------------------
// Main VQ: bf16 mma screening (best-4/lane) + exact fp32 verify + gather/loss
// Warp layout: wm = warp&3 -> rows 32*wm..+31 (two m16 frags);
//              wn = warp>>2 -> code half (512 codes each).
// ---------------------------------------------------------------------------
__global__ __launch_bounds__(256, 2) void vq_main(const float* __restrict__ z,
                                                  const float* __restrict__ emb,
                                                  float* __restrict__ out_zq,
                                                  float* __restrict__ out_idx) {
    extern __shared__ char smem_raw[];
    float*    zF   = (float*)   (smem_raw + SM_ZF);    // [128][68]
    float*    znS  = (float*)   (smem_raw + SM_ZN);
    unsigned* eB   = (unsigned*)(smem_raw + SM_EB);    // 2 x 4096 words
    float*    enS  = (float*)   (smem_raw + SM_EN);    // 2 x 128
    int*      idxS = (int*)     (smem_raw + SM_IDX);
    float*    pD   = (float*)   (smem_raw + SM_PD);    // [128][2]
    int*      pI   = (int*)     (smem_raw + SM_PI);
    float*    red  = (float*)   (smem_raw + SM_RED);

    const int tid  = threadIdx.x;
    const int lane = tid & 31;
    const int warp = tid >> 5;
    const int g    = lane >> 2;
    const int t2   = (lane & 3) * 2;         // col / k offset 2t
    const int wm   = warp & 3;               // m-quadrant (32 rows)
    const int wn   = warp >> 2;              // code half
    const int R0   = wm * 32;
    const int row0 = blockIdx.x * BM;

    // ---- prologue cp.async: zF tile, emb chunk 0, enorm chunk 0 ----
    #pragma unroll
    for (int i = 0; i < 8; ++i) {            // 2048 x 16B  (z: 128 rows x 256B)
        int u = tid + i * 256;
        int r = u >> 4, seg = u & 15;
        unsigned d = (unsigned)__cvta_generic_to_shared(zF + r * ZPAD + seg * 4);
        CP_ASYNC16(d, z + (size_t)(row0 + r) * DDIM + seg * 4);
    }
    #pragma unroll
    for (int i = 0; i < 4; ++i) {            // 1024 x 16B  (emb chunk = 16KB)
        int u = tid + i * 256;
        unsigned d = (unsigned)__cvta_generic_to_shared(eB + u * 4);
        CP_ASYNC16(d, g_embB + u * 4);
    }
    if (tid < 32) {                          // enorm chunk = 512B
        unsigned d = (unsigned)__cvta_generic_to_shared(enS + tid * 4);
        CP_ASYNC16(d, g_enorm + tid * 4);
    }
    CP_COMMIT();
    CP_WAIT0();
    __syncthreads();

    // ---- per-row ||z||^2 (sequential fp32, reference order) ----
    if (tid < BM) {
        const float* zr = zF + tid * ZPAD;
        float s = 0.0f;
        #pragma unroll
        for (int k = 0; k < DDIM; ++k)
            s = __fadd_rn(s, __fmul_rn(zr[k], zr[k]));
        znS[tid] = s;
    }

    // ---- build A fragments (two m16 frags, bf16) from zF ----
    unsigned aF[2][4][4];
    #pragma unroll
    for (int m2 = 0; m2 < 2; ++m2) {
        int ra = R0 + 16 * m2 + g;
        #pragma unroll
        for (int ks = 0; ks < 4; ++ks) {
            int k = 16 * ks + t2;
            aF[m2][ks][0] = pk_bf2(zF[ra * ZPAD + k],           zF[ra * ZPAD + k + 1]);
            aF[m2][ks][1] = pk_bf2(zF[(ra+8) * ZPAD + k],       zF[(ra+8) * ZPAD + k + 1]);
            aF[m2][ks][2] = pk_bf2(zF[ra * ZPAD + k + 8],       zF[ra * ZPAD + k + 9]);
            aF[m2][ks][3] = pk_bf2(zF[(ra+8) * ZPAD + k + 8],   zF[(ra+8) * ZPAD + k + 9]);
        }
    }

    // per-lane best-4 for 4 owned rows: sets {R0+g, R0+8+g, R0+16+g, R0+24+g}
    float bd[4][4];
    int   bi[4][4];
    #pragma unroll
    for (int s = 0; s < 4; ++s)
        #pragma unroll
        for (int j = 0; j < 4; ++j) { bd[s][j] = 3.402823466e38f; bi[s][j] = 0; }

    // ---- chunk loop: 8 chunks of 128 codes; warp handles its 8 n-frags ----
    for (int ch = 0; ch < NCH; ++ch) {
        if (ch + 1 < NCH) {
            unsigned* dstb = eB + ((ch + 1) & 1) * 4096;
            const unsigned* srcb = g_embB + (size_t)(ch + 1) * 4096;
            #pragma unroll
            for (int i = 0; i < 4; ++i) {
                int u = tid + i * 256;
                unsigned d = (unsigned)__cvta_generic_to_shared(dstb + u * 4);
                CP_ASYNC16(d, srcb + u * 4);
            }
            if (tid < 32) {
                unsigned d = (unsigned)__cvta_generic_to_shared(
                    enS + ((ch + 1) & 1) * 128 + tid * 4);
                CP_ASYNC16(d, g_enorm + (ch + 1) * 128 + tid * 4);
            }
            CP_COMMIT();
        }

        const unsigned* ebuf = eB  + (ch & 1) * 4096;
        const float*    ebn  = enS + (ch & 1) * 128;

        #pragma unroll
        for (int i = 0; i < 8; ++i) {
            int nf_l  = 8 * wn + i;
            int cbase = ch * CHCODES + nf_l * 8;

            const uint4* bp = (const uint4*)(ebuf + (nf_l * 32 + lane) * 8);
            uint4 bA = bp[0];      // ks0:{b0,b1}=x,y  ks1:{b0,b1}=z,w
            uint4 bB = bp[1];      // ks2, ks3
            float2 en2 = *(const float2*)(ebn + nf_l * 8 + t2);

            float c0[4] = {0.f, 0.f, 0.f, 0.f};
            float c1[4] = {0.f, 0.f, 0.f, 0.f};
            mma_bf16(c0, aF[0][0], bA.x, bA.y);  mma_bf16(c1, aF[1][0], bA.x, bA.y);
            mma_bf16(c0, aF[0][1], bA.z, bA.w);  mma_bf16(c1, aF[1][1], bA.z, bA.w);
            mma_bf16(c0, aF[0][2], bB.x, bB.y);  mma_bf16(c1, aF[1][2], bB.x, bB.y);
            mma_bf16(c0, aF[0][3], bB.z, bB.w);  mma_bf16(c1, aF[1][3], bB.z, bB.w);

            int i0 = cbase + t2, i1 = i0 + 1;
            ins4(__fmaf_rn(c0[0], -2.0f, en2.x), i0, bd[0], bi[0]);
            ins4(__fmaf_rn(c0[1], -2.0f, en2.y), i1, bd[0], bi[0]);
            ins4(__fmaf_rn(c0[2], -2.0f, en2.x), i0, bd[1], bi[1]);
            ins4(__fmaf_rn(c0[3], -2.0f, en2.y), i1, bd[1], bi[1]);
            ins4(__fmaf_rn(c1[0], -2.0f, en2.x), i0, bd[2], bi[2]);
            ins4(__fmaf_rn(c1[1], -2.0f, en2.y), i1, bd[2], bi[2]);
            ins4(__fmaf_rn(c1[2], -2.0f, en2.x), i0, bd[3], bi[3]);
            ins4(__fmaf_rn(c1[3], -2.0f, en2.y), i1, bd[3], bi[3]);
        }

        if (ch + 1 < NCH) {
            CP_WAIT0();
            __syncthreads();
        }
    }

    // ---- phase 2: exact verify of candidates within MARGIN of quad min ----
    #pragma unroll
    for (int s = 0; s < 4; ++s) {
        int rloc = R0 + ((s & 1) ? 8 : 0) + ((s >> 1) ? 16 : 0) + g;
        float gm = bd[s][0];
        gm = fminf(gm, __shfl_xor_sync(0xffffffffu, gm, 1));
        gm = fminf(gm, __shfl_xor_sync(0xffffffffu, gm, 2));
        float thr = gm + MARGIN;

        float bD = 3.402823466e38f;
        int   bI = 0x7fffffff;
        float zn = znS[rloc];
        const float* zrow = zF + rloc * ZPAD;
        if (bd[s][0] <= thr) exact_eval(zrow, emb, zn, bi[s][0], bD, bI);
        if (bd[s][1] <= thr) exact_eval(zrow, emb, zn, bi[s][1], bD, bI);
        if (bd[s][2] <= thr) exact_eval(zrow, emb, zn, bi[s][2], bD, bI);
        if (bd[s][3] <= thr) exact_eval(zrow, emb, zn, bi[s][3], bD, bI);

        // lexicographic (dist, idx) quad reduce
        #pragma unroll
        for (int m = 1; m <= 2; m <<= 1) {
            float oD = __shfl_xor_sync(0xffffffffu, bD, m);
            int   oI = __shfl_xor_sync(0xffffffffu, bI, m);
            if (oD < bD || (oD == bD && oI < bI)) { bD = oD; bI = oI; }
        }
        if ((lane & 3) == 0) { pD[rloc * 2 + wn] = bD; pI[rloc * 2 + wn] = bI; }
    }
    __syncthreads();

    // merge the two code-halves per row
    if (tid < BM) {
        float D0 = pD[tid * 2], D1 = pD[tid * 2 + 1];
        int   I0 = pI[tid * 2], I1 = pI[tid * 2 + 1];
        idxS[tid] = (D1 < D0 || (D1 == D0 && I1 < I0)) ? I1 : I0;
    }
    __syncthreads();

    // ---- gather z_q = emb[idx], write idx, accumulate (z_q - z)^2 ----
    {
        int   r    = tid >> 1;                 // row 0..127, 2 threads per row
        int   q    = tid & 1;                  // half of headdim
        int   ix   = idxS[r];
        int   grow = row0 + r;
        float psum = 0.0f;
        #pragma unroll
        for (int s4 = 0; s4 < 8; ++s4) {
            int d0 = q * 32 + s4 * 4;
            float4 e4 = *(const float4*)(emb + (size_t)ix * DDIM + d0);
            float4 z4 = *(const float4*)(zF + r * ZPAD + d0);
            float dx = __fadd_rn(e4.x, -z4.x);
            float dy = __fadd_rn(e4.y, -z4.y);
            float dz = __fadd_rn(e4.z, -z4.z);
            float dw = __fadd_rn(e4.w, -z4.w);
            psum = __fmaf_rn(dx, dx, psum);
            psum = __fmaf_rn(dy, dy, psum);
            psum = __fmaf_rn(dz, dz, psum);
            psum = __fmaf_rn(dw, dw, psum);
            *(float4*)(out_zq + (size_t)grow * DDIM + d0) = e4;
        }
        if (q == 0) out_idx[grow] = (float)ix;
        red[tid] = psum;
    }
    __syncthreads();
    #pragma unroll
    for (int s = 128; s > 0; s >>= 1) {
        if (tid < s) red[tid] = __fadd_rn(red[tid], red[tid + s]);
        __syncthreads();
    }
    if (tid == 0) g_partial[blockIdx.x] = red[0];
}

// ---------------------------------------------------------------------------
// Deterministic loss reduction: loss = 1.25 * (global sq sum) / (T*D)
// ---------------------------------------------------------------------------
__global__ __launch_bounds__(256) void loss_kernel(float* __restrict__ out_loss) {
    __shared__ float s[256];
    int tid = threadIdx.x;
    float v = __fadd_rn(g_partial[tid], g_partial[tid + 256]);
    s[tid] = v;
    __syncthreads();
    #pragma unroll
    for (int t = 128; t > 0; t >>= 1) {
        if (tid < t) s[tid] = __fadd_rn(s[tid], s[tid + t]);
        __syncthreads();
    }
    if (tid == 0)
        out_loss[0] = 1.25f * (s[0] * (1.0f / 262144.0f));  // 1/(4096*64)
}

// ---------------------------------------------------------------------------
extern "C" void kernel_launch(void* const* d_in, const int* in_sizes, int n_in,
                              void* d_out, int out_size) {
    const float* a0 = (const float*)d_in[0];
    const float* a1 = (const float*)d_in[1];
    const float* z;
    const float* emb;
    if (in_sizes[0] == BT * DDIM) { z = a0; emb = a1; }
    else                          { z = a1; emb = a0; }

    float* out      = (float*)d_out;
    float* out_zq   = out;                                  // 4,194,304
    float* out_loss = out + (size_t)BT * DDIM;              // 1
    float* out_idx  = out + (size_t)BT * DDIM + 1;          // 65,536

    cudaFuncSetAttribute(vq_main, cudaFuncAttributeMaxDynamicSharedMemorySize,
                         SMEM_TOTAL);

    prep_kernel<<<KCODES / 128, 128>>>(emb);
    vq_main<<<BT / BM, 256, SMEM_TOTAL>>>(z, emb, out_zq, out_idx);
    loss_kernel<<<1, 256>>>(out_loss);
}